// round 2
// baseline (speedup 1.0000x reference)
#include <cuda_runtime.h>

#define BATCH 4
#define CH 128
#define HH 96
#define WW 96
#define HW (HH*WW)
#define EPSBN 1e-5f

#define SP 68    // sample smem pitch (mult of 4 -> float4 aligned)
#define WP 132   // weight smem pitch
#define SMEM_DYN ((CH*SP + CH*WP)*4)

// ------------------ scratch: static device globals (no allocation) ----------
__device__ float g_xc [BATCH*CH*HW];   // x_c NCHW
__device__ float g_xn [BATCH*HW*CH];   // x_c NHWC (coalesced bilinear gather)
__device__ float g_off[BATCH*18*HW];   // offset conv output
__device__ float g_wdT[9*CH*CH];       // w_def  -> [n][ci][co]
__device__ float g_wsT[9*CH*CH];       // w_std  -> [k][ci][co]
__device__ float g_x1 [BATCH*CH*HW];   // deform branch post BN+ReLU
__device__ float g_x2c[BATCH*CH*HW];   // std branch post BN+ReLU + x_c

#define FMA4(A,S,V) { (A).x += (S)*(V).x; (A).y += (S)*(V).y; (A).z += (S)*(V).z; (A).w += (S)*(V).w; }

// ------------------ k_prep: weight transposes -------------------------------
__global__ void k_prep(const float* __restrict__ wdef, const float* __restrict__ wstd) {
    int i = blockIdx.x * 256 + threadIdx.x;
    if (i >= 9*CH*CH) return;
    int co = i & 127;
    int t  = i >> 7;          // n*128 + ci
    int n  = t >> 7, ci = t & 127;
    int src = co*1152 + ci*9 + n;
    g_wdT[i] = wdef[src];
    g_wsT[i] = wstd[src];
}

// ------------------ k_conv_in: 1x1 conv 128->128, NCHW + NHWC out -----------
__global__ __launch_bounds__(256) void k_conv_in(const float* __restrict__ x,
                                                 const float* __restrict__ w,
                                                 const float* __restrict__ bias) {
    __shared__ float Ws[32*WP];
    __shared__ float Xs[32*64];
    int tid = threadIdx.x;
    int b  = blockIdx.y;
    int p0 = blockIdx.x * 64;
    int ty = tid >> 4, tx = tid & 15;
    int cob = ty*8, pxb = tx*4;

    float4 a[8];
#pragma unroll
    for (int u = 0; u < 8; u++) a[u] = make_float4(0.f,0.f,0.f,0.f);

    for (int cb = 0; cb < CH; cb += 32) {
        __syncthreads();
        for (int idx = tid; idx < 4096; idx += 256) {
            int co = idx >> 5, c = idx & 31;
            Ws[c*WP + co] = w[co*CH + cb + c];
        }
        for (int idx = tid; idx < 2048; idx += 256) {
            int c = idx >> 6, p = idx & 63;
            Xs[c*64 + p] = x[((size_t)b*CH + cb + c)*HW + p0 + p];
        }
        __syncthreads();
#pragma unroll 8
        for (int c = 0; c < 32; c++) {
            float4 xv = *(float4*)&Xs[c*64 + pxb];
            float4 w0 = *(float4*)&Ws[c*WP + cob];
            float4 w1 = *(float4*)&Ws[c*WP + cob + 4];
            FMA4(a[0], w0.x, xv); FMA4(a[1], w0.y, xv);
            FMA4(a[2], w0.z, xv); FMA4(a[3], w0.w, xv);
            FMA4(a[4], w1.x, xv); FMA4(a[5], w1.y, xv);
            FMA4(a[6], w1.z, xv); FMA4(a[7], w1.w, xv);
        }
    }
    float bb[8];
#pragma unroll
    for (int u = 0; u < 8; u++) bb[u] = __ldg(&bias[cob + u]);
#pragma unroll
    for (int u = 0; u < 8; u++) {
        float4 o = a[u];
        o.x += bb[u]; o.y += bb[u]; o.z += bb[u]; o.w += bb[u];
        *(float4*)&g_xc[((size_t)b*CH + cob + u)*HW + p0 + pxb] = o;
    }
#define NSTORE(COMP, V) { \
        float4 o0 = make_float4(a[0].COMP+bb[0], a[1].COMP+bb[1], a[2].COMP+bb[2], a[3].COMP+bb[3]); \
        float4 o1 = make_float4(a[4].COMP+bb[4], a[5].COMP+bb[5], a[6].COMP+bb[6], a[7].COMP+bb[7]); \
        float* np = g_xn + ((size_t)(b*HW) + p0 + pxb + (V))*CH + cob; \
        *(float4*)np = o0; *(float4*)(np+4) = o1; }
    NSTORE(x, 0) NSTORE(y, 1) NSTORE(z, 2) NSTORE(w, 3)
#undef NSTORE
}

// ------------------ k_off: 3x3 conv 128->18 (offsets), pad=1 ----------------
__global__ __launch_bounds__(96) void k_off(const float* __restrict__ w,
                                            const float* __restrict__ bias) {
    __shared__ float ws[1152*9];    // [ci*9+k][co_local]
    int tid = threadIdx.x;
    int i = blockIdx.x, b = blockIdx.y, cog = blockIdx.z;   // cog in {0,1}
    for (int idx = tid; idx < 10368; idx += 96) {
        int co = idx / 1152, cik = idx % 1152;
        ws[cik*9 + co] = w[(cog*9 + co)*1152 + cik];
    }
    __syncthreads();
    int j = tid;
    float acc[9];
#pragma unroll
    for (int c = 0; c < 9; c++) acc[c] = 0.f;
    const float* xb = g_xc + (size_t)b*CH*HW;
    for (int ci = 0; ci < CH; ci++) {
#pragma unroll
        for (int kh = 0; kh < 3; kh++) {
            int row = i + kh - 1;
            bool rok = ((unsigned)row < 96u);
            const float* xr = xb + (size_t)ci*HW + row*WW;
#pragma unroll
            for (int kw = 0; kw < 3; kw++) {
                int col = j + kw - 1;
                float xv = (rok && (unsigned)col < 96u) ? xr[col] : 0.f;
                int wb = (ci*9 + kh*3 + kw)*9;
#pragma unroll
                for (int c = 0; c < 9; c++) acc[c] += ws[wb + c] * xv;
            }
        }
    }
#pragma unroll
    for (int c = 0; c < 9; c++)
        g_off[(size_t)((b*18 + cog*9 + c)*HH + i)*WW + j] = acc[c] + __ldg(&bias[cog*9 + c]);
}

// ------------------ k_deform: bilinear gather + K=1152 GEMM + BN1/ReLU ------
__global__ __launch_bounds__(256,2) void k_deform(const float* __restrict__ bdef,
                                                  const float* __restrict__ bn1) {
    extern __shared__ float sm[];
    float* s  = sm;            // [128][SP]
    float* ws = sm + CH*SP;    // [128][WP]
    int tid = threadIdx.x;
    int b  = blockIdx.y;
    int p0 = blockIdx.x * 64;
    int warp = tid >> 5, lane = tid & 31;
    int ty = tid >> 4, tx = tid & 15;
    int cob = ty*8, pxb = tx*4;

    float4 a[8];
#pragma unroll
    for (int u = 0; u < 8; u++) a[u] = make_float4(0.f,0.f,0.f,0.f);
    const float* xnb = g_xn + (size_t)b*HW*CH;

    for (int n = 0; n < 9; n++) {
        __syncthreads();
        // stage weights [ci][co] for this tap
        for (int idx = tid*4; idx < 16384; idx += 1024) {
            float4 v = *(const float4*)&g_wdT[n*16384 + idx];
            int ci = idx >> 7, co = idx & 127;
            *(float4*)&ws[ci*WP + co] = v;
        }
        // stage bilinear samples: warp per pixel, lanes over channels
        float dnx = (float)(n/3 - 1), dny = (float)(n%3 - 1);
#pragma unroll
        for (int k = 0; k < 8; k++) {
            int px = warp*8 + k;
            int pix = p0 + px;
            int i = pix / 96, j = pix - i*96;
            float ox = __ldg(&g_off[(size_t)(b*18 + n    )*HW + pix]);
            float oy = __ldg(&g_off[(size_t)(b*18 + n + 9)*HW + pix]);
            float pfx = ox + dnx + (float)(i + 1);
            float pfy = oy + dny + (float)(j + 1);
            float qx = floorf(pfx), qy = floorf(pfy);
            float ltx = fminf(fmaxf(qx,       0.f), 97.f);
            float lty = fminf(fmaxf(qy,       0.f), 97.f);
            float rbx = fminf(fmaxf(qx + 1.f, 0.f), 97.f);
            float rby = fminf(fmaxf(qy + 1.f, 0.f), 97.f);
            float pcx = fminf(fmaxf(pfx, 0.f), 97.f);
            float pcy = fminf(fmaxf(pfy, 0.f), 97.f);
            float glt = (1.f + (ltx - pcx)) * (1.f + (lty - pcy));
            float grb = (1.f - (rbx - pcx)) * (1.f - (rby - pcy));
            float glb = (1.f + (ltx - pcx)) * (1.f - (rby - pcy));
            float grt = (1.f - (rbx - pcx)) * (1.f + (lty - pcy));
            int ax = (int)ltx - 1, ay = (int)lty - 1;
            int bx = (int)rbx - 1, by = (int)rby - 1;
            bool vax = ((unsigned)ax < 96u), vay = ((unsigned)ay < 96u);
            bool vbx = ((unsigned)bx < 96u), vby = ((unsigned)by < 96u);
            bool v_lt = vax && vay, v_rb = vbx && vby;
            bool v_lb = vax && vby, v_rt = vbx && vay;
            const float* plt = xnb + (size_t)(ax*96 + ay)*CH;
            const float* prb = xnb + (size_t)(bx*96 + by)*CH;
            const float* plb = xnb + (size_t)(ax*96 + by)*CH;
            const float* prt = xnb + (size_t)(bx*96 + ay)*CH;
#pragma unroll
            for (int it = 0; it < 4; it++) {
                int ci = it*32 + lane;
                float v = 0.f;
                if (v_lt) v += glt * plt[ci];
                if (v_rb) v += grb * prb[ci];
                if (v_lb) v += glb * plb[ci];
                if (v_rt) v += grt * prt[ci];
                s[ci*SP + px] = v;
            }
        }
        __syncthreads();
#pragma unroll 8
        for (int c = 0; c < CH; c++) {
            float4 xv = *(float4*)&s[c*SP + pxb];
            float4 w0 = *(float4*)&ws[c*WP + cob];
            float4 w1 = *(float4*)&ws[c*WP + cob + 4];
            FMA4(a[0], w0.x, xv); FMA4(a[1], w0.y, xv);
            FMA4(a[2], w0.z, xv); FMA4(a[3], w0.w, xv);
            FMA4(a[4], w1.x, xv); FMA4(a[5], w1.y, xv);
            FMA4(a[6], w1.z, xv); FMA4(a[7], w1.w, xv);
        }
    }
    // epilogue: +bias, BN1, ReLU
#pragma unroll
    for (int u = 0; u < 8; u++) {
        int co = cob + u;
        float inv = __ldg(&bn1[co]) / sqrtf(__ldg(&bn1[384 + co]) + EPSBN);
        float add = __ldg(&bn1[128 + co]) - __ldg(&bn1[256 + co]) * inv;
        float bi  = __ldg(&bdef[co]);
        float4 o = a[u];
        o.x = fmaxf((o.x + bi)*inv + add, 0.f);
        o.y = fmaxf((o.y + bi)*inv + add, 0.f);
        o.z = fmaxf((o.z + bi)*inv + add, 0.f);
        o.w = fmaxf((o.w + bi)*inv + add, 0.f);
        *(float4*)&g_x1[((size_t)b*CH + co)*HW + p0 + pxb] = o;
    }
}

// ------------------ k_std: 3x3 conv + BN2/ReLU + residual add ---------------
__global__ __launch_bounds__(256,2) void k_std(const float* __restrict__ bstd,
                                               const float* __restrict__ bn2) {
    extern __shared__ float sm[];
    float* s  = sm;
    float* ws = sm + CH*SP;
    int tid = threadIdx.x;
    int b  = blockIdx.y;
    int p0 = blockIdx.x * 64;
    int ty = tid >> 4, tx = tid & 15;
    int cob = ty*8, pxb = tx*4;

    float4 a[8];
#pragma unroll
    for (int u = 0; u < 8; u++) a[u] = make_float4(0.f,0.f,0.f,0.f);

    for (int n = 0; n < 9; n++) {
        __syncthreads();
        for (int idx = tid*4; idx < 16384; idx += 1024) {
            float4 v = *(const float4*)&g_wsT[n*16384 + idx];
            int ci = idx >> 7, co = idx & 127;
            *(float4*)&ws[ci*WP + co] = v;
        }
        int di = n/3 - 1, dj = n%3 - 1;
        for (int idx = tid; idx < 8192; idx += 256) {
            int ci = idx >> 6, px = idx & 63;
            int pix = p0 + px;
            int i = pix / 96, j = pix - i*96;
            int ii = i + di, jj = j + dj;
            float v = ((unsigned)ii < 96u && (unsigned)jj < 96u)
                      ? g_xc[((size_t)b*CH + ci)*HW + ii*WW + jj] : 0.f;
            s[ci*SP + px] = v;
        }
        __syncthreads();
#pragma unroll 8
        for (int c = 0; c < CH; c++) {
            float4 xv = *(float4*)&s[c*SP + pxb];
            float4 w0 = *(float4*)&ws[c*WP + cob];
            float4 w1 = *(float4*)&ws[c*WP + cob + 4];
            FMA4(a[0], w0.x, xv); FMA4(a[1], w0.y, xv);
            FMA4(a[2], w0.z, xv); FMA4(a[3], w0.w, xv);
            FMA4(a[4], w1.x, xv); FMA4(a[5], w1.y, xv);
            FMA4(a[6], w1.z, xv); FMA4(a[7], w1.w, xv);
        }
    }
#pragma unroll
    for (int u = 0; u < 8; u++) {
        int co = cob + u;
        float inv = __ldg(&bn2[co]) / sqrtf(__ldg(&bn2[384 + co]) + EPSBN);
        float add = __ldg(&bn2[128 + co]) - __ldg(&bn2[256 + co]) * inv;
        float bi  = __ldg(&bstd[co]);
        float4 xc = *(float4*)&g_xc[((size_t)b*CH + co)*HW + p0 + pxb];
        float4 o = a[u];
        o.x = fmaxf((o.x + bi)*inv + add, 0.f) + xc.x;
        o.y = fmaxf((o.y + bi)*inv + add, 0.f) + xc.y;
        o.z = fmaxf((o.z + bi)*inv + add, 0.f) + xc.z;
        o.w = fmaxf((o.w + bi)*inv + add, 0.f) + xc.w;
        *(float4*)&g_x2c[((size_t)b*CH + co)*HW + p0 + pxb] = o;
    }
}

// ------------------ k_out: final 1x1 conv 256->256 --------------------------
__global__ __launch_bounds__(256) void k_out(const float* __restrict__ w,
                                             const float* __restrict__ bias,
                                             float* __restrict__ out) {
    __shared__ float Ws[32*WP];
    __shared__ float Xs[32*SP];
    int tid = threadIdx.x;
    int b  = blockIdx.y;
    int z  = blockIdx.z;              // co half: 0 -> 0..127, 1 -> 128..255
    int p0 = blockIdx.x * 64;
    int ty = tid >> 4, tx = tid & 15;
    int cob = ty*8, pxb = tx*4;

    float4 a[8];
#pragma unroll
    for (int u = 0; u < 8; u++) a[u] = make_float4(0.f,0.f,0.f,0.f);

    for (int cb = 0; cb < 256; cb += 32) {
        __syncthreads();
        for (int idx = tid; idx < 4096; idx += 256) {
            int co = idx >> 5, c = idx & 31;
            Ws[c*WP + co] = w[(z*128 + co)*256 + cb + c];
        }
        const float* src = (cb < 128) ? g_x1 + ((size_t)b*CH + cb)*HW
                                      : g_x2c + ((size_t)b*CH + cb - 128)*HW;
        for (int idx = tid; idx < 2048; idx += 256) {
            int c = idx >> 6, p = idx & 63;
            Xs[c*SP + p] = src[(size_t)c*HW + p0 + p];
        }
        __syncthreads();
#pragma unroll 8
        for (int c = 0; c < 32; c++) {
            float4 xv = *(float4*)&Xs[c*SP + pxb];
            float4 w0 = *(float4*)&Ws[c*WP + cob];
            float4 w1 = *(float4*)&Ws[c*WP + cob + 4];
            FMA4(a[0], w0.x, xv); FMA4(a[1], w0.y, xv);
            FMA4(a[2], w0.z, xv); FMA4(a[3], w0.w, xv);
            FMA4(a[4], w1.x, xv); FMA4(a[5], w1.y, xv);
            FMA4(a[6], w1.z, xv); FMA4(a[7], w1.w, xv);
        }
    }
#pragma unroll
    for (int u = 0; u < 8; u++) {
        float bi = __ldg(&bias[z*128 + cob + u]);
        float4 o = a[u];
        o.x += bi; o.y += bi; o.z += bi; o.w += bi;
        *(float4*)&out[((size_t)(b*256 + z*128 + cob + u))*HW + p0 + pxb] = o;
    }
}

// ------------------ launch ---------------------------------------------------
extern "C" void kernel_launch(void* const* d_in, const int* in_sizes, int n_in,
                              void* d_out, int out_size) {
    const float* x     = (const float*)d_in[0];
    const float* w_in  = (const float*)d_in[1];
    const float* b_in  = (const float*)d_in[2];
    const float* w_off = (const float*)d_in[3];
    const float* b_off = (const float*)d_in[4];
    const float* w_def = (const float*)d_in[5];
    const float* b_def = (const float*)d_in[6];
    const float* bn1   = (const float*)d_in[7];
    const float* w_std = (const float*)d_in[8];
    const float* b_std = (const float*)d_in[9];
    const float* bn2   = (const float*)d_in[10];
    const float* w_out = (const float*)d_in[11];
    const float* b_out = (const float*)d_in[12];
    float* out = (float*)d_out;

    cudaFuncSetAttribute(k_deform, cudaFuncAttributeMaxDynamicSharedMemorySize, SMEM_DYN);
    cudaFuncSetAttribute(k_std,    cudaFuncAttributeMaxDynamicSharedMemorySize, SMEM_DYN);

    k_prep   <<<576, 256>>>(w_def, w_std);
    k_conv_in<<<dim3(144, BATCH), 256>>>(x, w_in, b_in);
    k_off    <<<dim3(96, BATCH, 2), 96>>>(w_off, b_off);
    k_deform <<<dim3(144, BATCH), 256, SMEM_DYN>>>(b_def, bn1);
    k_std    <<<dim3(144, BATCH), 256, SMEM_DYN>>>(b_std, bn2);
    k_out    <<<dim3(144, BATCH, 2), 256>>>(w_out, b_out, out);
}

// round 3
// speedup vs baseline: 1.0575x; 1.0575x over previous
#include <cuda_runtime.h>

#define BATCH 4
#define CH 128
#define HH 96
#define WW 96
#define HW (HH*WW)
#define EPSBN 1e-5f

#define SP 68    // sample smem pitch (mult of 4 -> float4 aligned)
#define WP 132   // weight smem pitch
#define SMEM_DYN ((CH*SP + CH*WP)*4)

typedef unsigned long long u64;

// ------------------ packed f32x2 helpers ------------------------------------
__device__ __forceinline__ void fma2(u64 &d, u64 a, u64 b) {
    asm("fma.rn.f32x2 %0, %1, %2, %0;" : "+l"(d) : "l"(a), "l"(b));
}
__device__ __forceinline__ u64 bc2(float x) {
    u64 r; asm("mov.b64 %0, {%1, %1};" : "=l"(r) : "f"(x)); return r;
}
__device__ __forceinline__ float2 unp2(u64 v) {
    float2 f; asm("mov.b64 {%0, %1}, %2;" : "=f"(f.x), "=f"(f.y) : "l"(v)); return f;
}

// GEMM micro-step: acc[px][cp] += x[px] * w[cp], cp packs co pairs
#define GSTEP(SROW, WROW) { \
    float4 xv = *(const float4*)(SROW); \
    ulonglong2 wA = *(const ulonglong2*)(WROW); \
    ulonglong2 wB = *(const ulonglong2*)((WROW)+4); \
    u64 xb0=bc2(xv.x), xb1=bc2(xv.y), xb2=bc2(xv.z), xb3=bc2(xv.w); \
    fma2(acc[0][0],wA.x,xb0); fma2(acc[0][1],wA.y,xb0); fma2(acc[0][2],wB.x,xb0); fma2(acc[0][3],wB.y,xb0); \
    fma2(acc[1][0],wA.x,xb1); fma2(acc[1][1],wA.y,xb1); fma2(acc[1][2],wB.x,xb1); fma2(acc[1][3],wB.y,xb1); \
    fma2(acc[2][0],wA.x,xb2); fma2(acc[2][1],wA.y,xb2); fma2(acc[2][2],wB.x,xb2); fma2(acc[2][3],wB.y,xb2); \
    fma2(acc[3][0],wA.x,xb3); fma2(acc[3][1],wA.y,xb3); fma2(acc[3][2],wB.x,xb3); fma2(acc[3][3],wB.y,xb3); }

#define ACC_INIT u64 acc[4][4]; _Pragma("unroll") for (int _i=0;_i<4;_i++) _Pragma("unroll") for(int _j=0;_j<4;_j++) acc[_i][_j]=0ull;

// ------------------ scratch: static device globals (no allocation) ----------
__device__ float g_xc [BATCH*CH*HW];   // x_c NCHW
__device__ float g_xn [BATCH*HW*CH];   // x_c NHWC (coalesced bilinear gather)
__device__ float g_off[BATCH*18*HW];   // offset conv output
__device__ float g_wdT[9*CH*CH];       // w_def  -> [n][ci][co]
__device__ float g_wsT[9*CH*CH];       // w_std  -> [k][ci][co]
__device__ float g_x1 [BATCH*CH*HW];   // deform branch post BN+ReLU
__device__ float g_x2c[BATCH*CH*HW];   // std branch post BN+ReLU + x_c

// ------------------ k_prep: weight transposes -------------------------------
__global__ void k_prep(const float* __restrict__ wdef, const float* __restrict__ wstd) {
    int i = blockIdx.x * 256 + threadIdx.x;
    if (i >= 9*CH*CH) return;
    int co = i & 127;
    int t  = i >> 7;          // n*128 + ci
    int n  = t >> 7, ci = t & 127;
    int src = co*1152 + ci*9 + n;
    g_wdT[i] = wdef[src];
    g_wsT[i] = wstd[src];
}

// ------------------ k_conv_in: 1x1 conv 128->128, NCHW + NHWC out -----------
__global__ __launch_bounds__(256) void k_conv_in(const float* __restrict__ x,
                                                 const float* __restrict__ w,
                                                 const float* __restrict__ bias) {
    __shared__ float Ws[32*WP];
    __shared__ float Xs[32*64];
    int tid = threadIdx.x;
    int b  = blockIdx.y;
    int p0 = blockIdx.x * 64;
    int ty = tid >> 4, tx = tid & 15;
    int cob = ty*8, pxb = tx*4;

    ACC_INIT

    for (int cb = 0; cb < CH; cb += 32) {
        __syncthreads();
        for (int idx = tid; idx < 4096; idx += 256) {
            int co = idx >> 5, c = idx & 31;
            Ws[c*WP + co] = w[co*CH + cb + c];
        }
        for (int idx = tid; idx < 2048; idx += 256) {
            int c = idx >> 6, p = idx & 63;
            Xs[c*64 + p] = x[((size_t)b*CH + cb + c)*HW + p0 + p];
        }
        __syncthreads();
#pragma unroll 8
        for (int c = 0; c < 32; c++) {
            GSTEP(&Xs[c*64 + pxb], &Ws[c*WP + cob])
        }
    }
    // unpack to v[px][co_local]
    float v[4][8];
#pragma unroll
    for (int k = 0; k < 4; k++) {
#pragma unroll
        for (int px = 0; px < 4; px++) {
            float2 f = unp2(acc[px][k]);
            v[px][2*k] = f.x; v[px][2*k+1] = f.y;
        }
    }
    float bb[8];
#pragma unroll
    for (int u = 0; u < 8; u++) bb[u] = __ldg(&bias[cob + u]);
#pragma unroll
    for (int u = 0; u < 8; u++) {
        float4 o = make_float4(v[0][u]+bb[u], v[1][u]+bb[u], v[2][u]+bb[u], v[3][u]+bb[u]);
        *(float4*)&g_xc[((size_t)b*CH + cob + u)*HW + p0 + pxb] = o;
    }
#pragma unroll
    for (int px = 0; px < 4; px++) {
        float4 o0 = make_float4(v[px][0]+bb[0], v[px][1]+bb[1], v[px][2]+bb[2], v[px][3]+bb[3]);
        float4 o1 = make_float4(v[px][4]+bb[4], v[px][5]+bb[5], v[px][6]+bb[6], v[px][7]+bb[7]);
        float* np = g_xn + ((size_t)(b*HW) + p0 + pxb + px)*CH + cob;
        *(float4*)np = o0; *(float4*)(np+4) = o1;
    }
}

// ------------------ k_off: 3x3 conv 128->18 (offsets), pad=1 ----------------
__global__ __launch_bounds__(384) void k_off(const float* __restrict__ w,
                                             const float* __restrict__ bias) {
    __shared__ float ws[1152*9];    // [ci*9+k][co_local]
    int tid = threadIdx.x;
    int b = blockIdx.y, cog = blockIdx.z;   // cog in {0,1}
    for (int idx = tid; idx < 10368; idx += 384) {
        int co = idx / 1152, cik = idx % 1152;
        ws[cik*9 + co] = w[(cog*9 + co)*1152 + cik];
    }
    __syncthreads();
    int i = blockIdx.x*4 + tid/96;
    int j = tid % 96;
    float acc[9];
#pragma unroll
    for (int c = 0; c < 9; c++) acc[c] = 0.f;
    const float* xb = g_xc + (size_t)b*CH*HW;
    for (int ci = 0; ci < CH; ci++) {
#pragma unroll
        for (int kh = 0; kh < 3; kh++) {
            int row = i + kh - 1;
            bool rok = ((unsigned)row < 96u);
            const float* xr = xb + (size_t)ci*HW + row*WW;
#pragma unroll
            for (int kw = 0; kw < 3; kw++) {
                int col = j + kw - 1;
                float xv = (rok && (unsigned)col < 96u) ? xr[col] : 0.f;
                int wb = (ci*9 + kh*3 + kw)*9;
#pragma unroll
                for (int c = 0; c < 9; c++) acc[c] += ws[wb + c] * xv;
            }
        }
    }
#pragma unroll
    for (int c = 0; c < 9; c++)
        g_off[(size_t)((b*18 + cog*9 + c)*HH + i)*WW + j] = acc[c] + __ldg(&bias[cog*9 + c]);
}

// ------------------ k_deform: bilinear gather + K=1152 GEMM + BN1/ReLU ------
__global__ __launch_bounds__(256,2) void k_deform(const float* __restrict__ bdef,
                                                  const float* __restrict__ bn1) {
    extern __shared__ float sm[];
    float* s  = sm;            // [128][SP]
    float* ws = sm + CH*SP;    // [128][WP]
    int tid = threadIdx.x;
    int b  = blockIdx.y;
    int p0 = blockIdx.x * 64;
    int warp = tid >> 5, lane = tid & 31;
    int ty = tid >> 4, tx = tid & 15;
    int cob = ty*8, pxb = tx*4;

    ACC_INIT
    const float* xnb = g_xn + (size_t)b*HW*CH;

    for (int n = 0; n < 9; n++) {
        __syncthreads();
        // stage weights [ci][co] for this tap
        for (int idx = tid*4; idx < 16384; idx += 1024) {
            float4 wv = *(const float4*)&g_wdT[n*16384 + idx];
            int ci = idx >> 7, co = idx & 127;
            *(float4*)&ws[ci*WP + co] = wv;
        }
        // stage bilinear samples: warp per pixel, lanes over channels
        float dnx = (float)(n/3 - 1), dny = (float)(n%3 - 1);
#pragma unroll
        for (int k = 0; k < 8; k++) {
            int px = warp*8 + k;
            int pix = p0 + px;
            int i = pix / 96, j = pix - i*96;
            float ox = __ldg(&g_off[(size_t)(b*18 + n    )*HW + pix]);
            float oy = __ldg(&g_off[(size_t)(b*18 + n + 9)*HW + pix]);
            float pfx = ox + dnx + (float)(i + 1);
            float pfy = oy + dny + (float)(j + 1);
            float qx = floorf(pfx), qy = floorf(pfy);
            float ltx = fminf(fmaxf(qx,       0.f), 97.f);
            float lty = fminf(fmaxf(qy,       0.f), 97.f);
            float rbx = fminf(fmaxf(qx + 1.f, 0.f), 97.f);
            float rby = fminf(fmaxf(qy + 1.f, 0.f), 97.f);
            float pcx = fminf(fmaxf(pfx, 0.f), 97.f);
            float pcy = fminf(fmaxf(pfy, 0.f), 97.f);
            float glt = (1.f + (ltx - pcx)) * (1.f + (lty - pcy));
            float grb = (1.f - (rbx - pcx)) * (1.f - (rby - pcy));
            float glb = (1.f + (ltx - pcx)) * (1.f - (rby - pcy));
            float grt = (1.f - (rbx - pcx)) * (1.f + (lty - pcy));
            int ax = (int)ltx - 1, ay = (int)lty - 1;
            int bx = (int)rbx - 1, by = (int)rby - 1;
            bool vax = ((unsigned)ax < 96u), vay = ((unsigned)ay < 96u);
            bool vbx = ((unsigned)bx < 96u), vby = ((unsigned)by < 96u);
            bool v_lt = vax && vay, v_rb = vbx && vby;
            bool v_lb = vax && vby, v_rt = vbx && vay;
            const float* plt = xnb + (size_t)(ax*96 + ay)*CH;
            const float* prb = xnb + (size_t)(bx*96 + by)*CH;
            const float* plb = xnb + (size_t)(ax*96 + by)*CH;
            const float* prt = xnb + (size_t)(bx*96 + ay)*CH;
#pragma unroll
            for (int it = 0; it < 4; it++) {
                int ci = it*32 + lane;
                float vv = 0.f;
                if (v_lt) vv += glt * plt[ci];
                if (v_rb) vv += grb * prb[ci];
                if (v_lb) vv += glb * plb[ci];
                if (v_rt) vv += grt * prt[ci];
                s[ci*SP + px] = vv;
            }
        }
        __syncthreads();
#pragma unroll 8
        for (int c = 0; c < CH; c++) {
            GSTEP(&s[c*SP + pxb], &ws[c*WP + cob])
        }
    }
    // epilogue: +bias, BN1, ReLU
#pragma unroll
    for (int k = 0; k < 4; k++) {
        float2 e0 = unp2(acc[0][k]), e1 = unp2(acc[1][k]);
        float2 e2 = unp2(acc[2][k]), e3 = unp2(acc[3][k]);
#pragma unroll
        for (int h = 0; h < 2; h++) {
            int co = cob + 2*k + h;
            float inv = __ldg(&bn1[co]) / sqrtf(__ldg(&bn1[384 + co]) + EPSBN);
            float add = __ldg(&bn1[128 + co]) - __ldg(&bn1[256 + co]) * inv;
            float bi  = __ldg(&bdef[co]);
            float4 o;
            if (h == 0) o = make_float4(e0.x, e1.x, e2.x, e3.x);
            else        o = make_float4(e0.y, e1.y, e2.y, e3.y);
            o.x = fmaxf((o.x + bi)*inv + add, 0.f);
            o.y = fmaxf((o.y + bi)*inv + add, 0.f);
            o.z = fmaxf((o.z + bi)*inv + add, 0.f);
            o.w = fmaxf((o.w + bi)*inv + add, 0.f);
            *(float4*)&g_x1[((size_t)b*CH + co)*HW + p0 + pxb] = o;
        }
    }
}

// ------------------ k_std: 3x3 conv + BN2/ReLU + residual add ---------------
__global__ __launch_bounds__(256,2) void k_std(const float* __restrict__ bstd,
                                               const float* __restrict__ bn2) {
    extern __shared__ float sm[];
    float* s  = sm;
    float* ws = sm + CH*SP;
    int tid = threadIdx.x;
    int b  = blockIdx.y;
    int p0 = blockIdx.x * 64;
    int ty = tid >> 4, tx = tid & 15;
    int cob = ty*8, pxb = tx*4;

    ACC_INIT

    for (int n = 0; n < 9; n++) {
        __syncthreads();
        for (int idx = tid*4; idx < 16384; idx += 1024) {
            float4 wv = *(const float4*)&g_wsT[n*16384 + idx];
            int ci = idx >> 7, co = idx & 127;
            *(float4*)&ws[ci*WP + co] = wv;
        }
        int di = n/3 - 1, dj = n%3 - 1;
        for (int idx = tid; idx < 8192; idx += 256) {
            int ci = idx >> 6, px = idx & 63;
            int pix = p0 + px;
            int i = pix / 96, j = pix - i*96;
            int ii = i + di, jj = j + dj;
            float vv = ((unsigned)ii < 96u && (unsigned)jj < 96u)
                      ? g_xc[((size_t)b*CH + ci)*HW + ii*WW + jj] : 0.f;
            s[ci*SP + px] = vv;
        }
        __syncthreads();
#pragma unroll 8
        for (int c = 0; c < CH; c++) {
            GSTEP(&s[c*SP + pxb], &ws[c*WP + cob])
        }
    }
#pragma unroll
    for (int k = 0; k < 4; k++) {
        float2 e0 = unp2(acc[0][k]), e1 = unp2(acc[1][k]);
        float2 e2 = unp2(acc[2][k]), e3 = unp2(acc[3][k]);
#pragma unroll
        for (int h = 0; h < 2; h++) {
            int co = cob + 2*k + h;
            float inv = __ldg(&bn2[co]) / sqrtf(__ldg(&bn2[384 + co]) + EPSBN);
            float add = __ldg(&bn2[128 + co]) - __ldg(&bn2[256 + co]) * inv;
            float bi  = __ldg(&bstd[co]);
            float4 xc = *(float4*)&g_xc[((size_t)b*CH + co)*HW + p0 + pxb];
            float4 o;
            if (h == 0) o = make_float4(e0.x, e1.x, e2.x, e3.x);
            else        o = make_float4(e0.y, e1.y, e2.y, e3.y);
            o.x = fmaxf((o.x + bi)*inv + add, 0.f) + xc.x;
            o.y = fmaxf((o.y + bi)*inv + add, 0.f) + xc.y;
            o.z = fmaxf((o.z + bi)*inv + add, 0.f) + xc.z;
            o.w = fmaxf((o.w + bi)*inv + add, 0.f) + xc.w;
            *(float4*)&g_x2c[((size_t)b*CH + co)*HW + p0 + pxb] = o;
        }
    }
}

// ------------------ k_out: final 1x1 conv 256->256 --------------------------
__global__ __launch_bounds__(256) void k_out(const float* __restrict__ w,
                                             const float* __restrict__ bias,
                                             float* __restrict__ out) {
    __shared__ float Ws[32*WP];
    __shared__ float Xs[32*SP];
    int tid = threadIdx.x;
    int b  = blockIdx.y;
    int z  = blockIdx.z;              // co half: 0 -> 0..127, 1 -> 128..255
    int p0 = blockIdx.x * 64;
    int ty = tid >> 4, tx = tid & 15;
    int cob = ty*8, pxb = tx*4;

    ACC_INIT

    for (int cb = 0; cb < 256; cb += 32) {
        __syncthreads();
        for (int idx = tid; idx < 4096; idx += 256) {
            int co = idx >> 5, c = idx & 31;
            Ws[c*WP + co] = w[(z*128 + co)*256 + cb + c];
        }
        const float* src = (cb < 128) ? g_x1 + ((size_t)b*CH + cb)*HW
                                      : g_x2c + ((size_t)b*CH + cb - 128)*HW;
        for (int idx = tid; idx < 2048; idx += 256) {
            int c = idx >> 6, p = idx & 63;
            Xs[c*SP + p] = src[(size_t)c*HW + p0 + p];
        }
        __syncthreads();
#pragma unroll 8
        for (int c = 0; c < 32; c++) {
            GSTEP(&Xs[c*SP + pxb], &Ws[c*WP + cob])
        }
    }
#pragma unroll
    for (int k = 0; k < 4; k++) {
        float2 e0 = unp2(acc[0][k]), e1 = unp2(acc[1][k]);
        float2 e2 = unp2(acc[2][k]), e3 = unp2(acc[3][k]);
#pragma unroll
        for (int h = 0; h < 2; h++) {
            int co = cob + 2*k + h;
            float bi = __ldg(&bias[z*128 + co]);
            float4 o;
            if (h == 0) o = make_float4(e0.x, e1.x, e2.x, e3.x);
            else        o = make_float4(e0.y, e1.y, e2.y, e3.y);
            o.x += bi; o.y += bi; o.z += bi; o.w += bi;
            *(float4*)&out[((size_t)(b*256 + z*128 + co))*HW + p0 + pxb] = o;
        }
    }
}

// ------------------ launch ---------------------------------------------------
extern "C" void kernel_launch(void* const* d_in, const int* in_sizes, int n_in,
                              void* d_out, int out_size) {
    const float* x     = (const float*)d_in[0];
    const float* w_in  = (const float*)d_in[1];
    const float* b_in  = (const float*)d_in[2];
    const float* w_off = (const float*)d_in[3];
    const float* b_off = (const float*)d_in[4];
    const float* w_def = (const float*)d_in[5];
    const float* b_def = (const float*)d_in[6];
    const float* bn1   = (const float*)d_in[7];
    const float* w_std = (const float*)d_in[8];
    const float* b_std = (const float*)d_in[9];
    const float* bn2   = (const float*)d_in[10];
    const float* w_out = (const float*)d_in[11];
    const float* b_out = (const float*)d_in[12];
    float* out = (float*)d_out;

    cudaFuncSetAttribute(k_deform, cudaFuncAttributeMaxDynamicSharedMemorySize, SMEM_DYN);
    cudaFuncSetAttribute(k_std,    cudaFuncAttributeMaxDynamicSharedMemorySize, SMEM_DYN);

    k_prep   <<<576, 256>>>(w_def, w_std);
    k_conv_in<<<dim3(144, BATCH), 256>>>(x, w_in, b_in);
    k_off    <<<dim3(24, BATCH, 2), 384>>>(w_off, b_off);
    k_deform <<<dim3(144, BATCH), 256, SMEM_DYN>>>(b_def, bn1);
    k_std    <<<dim3(144, BATCH), 256, SMEM_DYN>>>(b_std, bn2);
    k_out    <<<dim3(144, BATCH, 2), 256>>>(w_out, b_out, out);
}